// round 16
// baseline (speedup 1.0000x reference)
#include <cuda_runtime.h>
#include <cuda_bf16.h>
#include <math.h>

// ---------------- problem constants ----------------
#define BB_   8
#define NTOK  196
#define DD    768
#define NH    12
#define HD    64
#define MHOP  3072
#define BN    (BB_*NTOK)          // 1568
#define NELEM (BN*DD)             // 1204224
#define KCAT  4608                // 768 + 768 + 3072
#define BETA  0.125f
#define INVB  8.0f

typedef __nv_bfloat16 bf16;

// ---------------- scratch ----------------
__device__ __align__(256) bf16  d_ghi[4L*BN*DD];
__device__ __align__(256) bf16  d_glo[(long)BN*DD];
__device__ __align__(256) float d_K  [4L*BN*DD];
__device__ __align__(256) float d_Q  [4L*BN*DD];
__device__ __align__(256) bf16  d_Ahi[(long)BN*KCAT];    // [dK | dQ | h] hi
__device__ __align__(256) bf16  d_Alo[(long)BN*KCAT];    // lo
__device__ __align__(256) bf16  d_whi[(long)KCAT*DD];    // [wk|wq|xi] hi
__device__ __align__(256) bf16  d_wlo[(long)KCAT*DD];
__device__ __align__(256) bf16  d_BThi[(long)DD*KCAT];   // [WkT|WqT|-XiT] hi
__device__ __align__(256) bf16  d_BTlo[(long)DD*KCAT];
__device__ __align__(256) float d_dg [BN*DD];
__device__ __align__(256) float d_gr [BN*DD];
__device__ float  d_mean[BN];
__device__ float  d_rstd[BN];
__device__ double d_eref;
__device__ double d_ecand[4];
__constant__ float c_lrs[4] = {1.0f, 0.5f, 0.25f, 0.125f};

// ---------------- helpers ----------------
__device__ __forceinline__ void hsplit(float v, bf16& h, bf16& l) {
    h = __float2bfloat16_rn(v);
    l = __float2bfloat16_rn(v - __bfloat162float(h));
}

// ---------------- tiny kernels ----------------
__global__ void zero_kernel() {
    if (threadIdx.x == 0) d_eref = 0.0;
    if (threadIdx.x < 4)  d_ecand[threadIdx.x] = 0.0;
}

// update with inlined Armijo selection (each block recomputes; deterministic)
__global__ void update_kernel(const float* __restrict__ x,
                              const float* __restrict__ grad,
                              float* __restrict__ out) {
    __shared__ float chosen_s;
    if (threadIdx.x == 0) {
        double eref = d_eref;
        float chosen = 0.0625f;
        if (d_ecand[3] < eref) chosen = 0.125f;
        if (d_ecand[2] < eref) chosen = 0.25f;
        if (d_ecand[1] < eref) chosen = 0.5f;
        if (d_ecand[0] < eref) chosen = 1.0f;
        chosen_s = chosen;
    }
    __syncthreads();
    float ch = chosen_s;
    int i = blockIdx.x * 256 + threadIdx.x;
    if (i < NELEM) out[i] = x[i] - ch * grad[i];
}

// weights -> concat bf16 hi/lo  [4608][768]
__global__ void w2bf_kernel(const float* __restrict__ wk,
                            const float* __restrict__ wq,
                            const float* __restrict__ xi,
                            bf16* __restrict__ whi, bf16* __restrict__ wlo) {
    long i = (long)blockIdx.x * 256 + threadIdx.x;
    if (i >= (long)KCAT * DD) return;
    long n = i / DD;
    float v;
    if (n < DD)           v = wk[i];
    else if (n < 2 * DD)  v = wq[i - (long)DD * DD];
    else                  v = xi[i - 2L * DD * DD];
    bf16 h, l; hsplit(v, h, l);
    whi[i] = h; wlo[i] = l;
}

// outHi/Lo[d][colbase + r] = hi/lo(s * in[r][d]);   out row stride KCAT
__global__ void btprep_kernel(const float* __restrict__ in,
                              bf16* __restrict__ outHi, bf16* __restrict__ outLo,
                              int colbase, float s) {
    __shared__ float t[32][33];
    int d0 = blockIdx.x * 32, r0 = blockIdx.y * 32;
    int tx = threadIdx.x, ty = threadIdx.y;     // 32 x 8
#pragma unroll
    for (int i = 0; i < 4; i++) {
        int r = r0 + ty + i * 8;
        t[ty + i * 8][tx] = in[(long)r * DD + d0 + tx];
    }
    __syncthreads();
#pragma unroll
    for (int i = 0; i < 4; i++) {
        int d = d0 + ty + i * 8;
        float v = s * t[tx][ty + i * 8];
        bf16 h, l; hsplit(v, h, l);
        long o = (long)d * KCAT + colbase + r0 + tx;
        outHi[o] = h; outLo[o] = l;
    }
}

// ---------------- LayerNorm forward -> bf16 hi(/lo) ----------------
__global__ void ln_fwd_kernel(const float* __restrict__ x,
                              const float* __restrict__ grad,
                              bf16* __restrict__ ghi, bf16* __restrict__ glo,
                              const float* __restrict__ gamma,
                              const float* __restrict__ delta,
                              float* meanOut, float* rstdOut, int useLr) {
    int t = blockIdx.x, z = blockIdx.z, tid = threadIdx.x;
    const float lr = useLr ? c_lrs[z] : 0.f;
    const float* xr = x + (long)t * DD;
    float v[3]; float s = 0.f;
#pragma unroll
    for (int i = 0; i < 3; i++) {
        int c = tid + i * 256;
        float xv = xr[c];
        if (useLr) xv -= lr * grad[(long)t * DD + c];
        v[i] = xv; s += xv;
    }
    __shared__ float red[256];
    red[tid] = s; __syncthreads();
    for (int o = 128; o; o >>= 1) { if (tid < o) red[tid] += red[tid + o]; __syncthreads(); }
    float mu = red[0] * (1.f / DD);
    __syncthreads();
    float s2 = 0.f;
#pragma unroll
    for (int i = 0; i < 3; i++) { float dv = v[i] - mu; s2 += dv * dv; }
    red[tid] = s2; __syncthreads();
    for (int o = 128; o; o >>= 1) { if (tid < o) red[tid] += red[tid + o]; __syncthreads(); }
    float rs = rsqrtf(red[0] * (1.f / DD) + 1e-5f);
    long base = (long)z * NELEM + (long)t * DD;
#pragma unroll
    for (int i = 0; i < 3; i++) {
        int c = tid + i * 256;
        float gv = gamma[c] * (v[i] - mu) * rs + delta[c];
        bf16 h, l; hsplit(gv, h, l);
        ghi[base + c] = h;
        if (glo != nullptr) glo[(long)t * DD + c] = l;
    }
    if (!useLr && tid == 0) { meanOut[t] = mu; rstdOut[t] = rs; }
}

// ---------------- LayerNorm backward ----------------
__global__ void ln_bwd_kernel(const float* __restrict__ x,
                              const float* __restrict__ mean,
                              const float* __restrict__ rstd,
                              const float* __restrict__ gamma,
                              const float* __restrict__ dgv,
                              float* __restrict__ dx) {
    int t = blockIdx.x, tid = threadIdx.x;
    float mu = mean[t], rs = rstd[t];
    const float* xr = x + (long)t * DD;
    const float* dr = dgv + (long)t * DD;
    float xh[3], dxh[3]; float s1 = 0.f, s2 = 0.f;
#pragma unroll
    for (int i = 0; i < 3; i++) {
        int c = tid + i * 256;
        xh[i]  = (xr[c] - mu) * rs;
        dxh[i] = dr[c] * gamma[c];
        s1 += dxh[i]; s2 += dxh[i] * xh[i];
    }
    __shared__ float r1[256], r2[256];
    r1[tid] = s1; r2[tid] = s2; __syncthreads();
    for (int o = 128; o; o >>= 1) {
        if (tid < o) { r1[tid] += r1[tid + o]; r2[tid] += r2[tid + o]; }
        __syncthreads();
    }
    float m1 = r1[0] * (1.f / DD), m2 = r2[0] * (1.f / DD);
#pragma unroll
    for (int i = 0; i < 3; i++) {
        int c = tid + i * 256;
        dx[(long)t * DD + c] = rs * (dxh[i] - m1 - xh[i] * m2);
    }
}

// ---------------- bf16 GEMM: 128x128x32 tile, 128 thr (4 warps, 64x64 warp tile) ----------------
// cp.async + ldmatrix. Rows are 32 bf16 = 64B = 4 x 16B chunks;
// swizzle: line = row>>1 (128B), slot = (row&1)*4 + (ch ^ (line&3)).
// NTERM=3: acc += Ah*Bh + Ah*Bl + Al*Bh.  NTERM=1: single term.
// FUSED=1: concat-B [4608][K]: n0<768 -> CK float, n0<1536 -> CQ float, else epiH.
// FUSED=0: plain C=CK float ld DD (dgrad).
__device__ __forceinline__ void mma16(float* c, const unsigned* a, const unsigned* b) {
    asm volatile("mma.sync.aligned.m16n8k16.row.col.f32.bf16.bf16.f32 "
                 "{%0,%1,%2,%3}, {%4,%5,%6,%7}, {%8,%9}, {%0,%1,%2,%3};"
                 : "+f"(c[0]), "+f"(c[1]), "+f"(c[2]), "+f"(c[3])
                 : "r"(a[0]), "r"(a[1]), "r"(a[2]), "r"(a[3]),
                   "r"(b[0]), "r"(b[1]));
}

__device__ __forceinline__ void ldsm4(unsigned& r0, unsigned& r1, unsigned& r2, unsigned& r3,
                                      unsigned addr) {
    asm volatile("ldmatrix.sync.aligned.m8n8.x4.shared.b16 {%0,%1,%2,%3}, [%4];"
                 : "=r"(r0), "=r"(r1), "=r"(r2), "=r"(r3) : "r"(addr));
}

__device__ __forceinline__ void cpa16(unsigned sa, const void* ga, int sz) {
    asm volatile("cp.async.cg.shared.global [%0], [%1], 16, %2;"
                 :: "r"(sa), "l"(ga), "r"(sz));
}

template <int NTERM, int FUSED>
__global__ void __launch_bounds__(128, 2)
gemm_k(const bf16* __restrict__ Ahi, const bf16* __restrict__ Alo,
       const bf16* __restrict__ Bhi, const bf16* __restrict__ Blo,
       float* __restrict__ CK, float* __restrict__ CQ,
       bf16* __restrict__ CHhi, bf16* __restrict__ CHlo,
       int Mrows, int Kdim, int epiH,
       double* e_base, int e_per_z, long strideAz, long strideCz) {
    constexpr int NS = (NTERM == 3) ? 2 : 1;
    // A: 128 rows x 32 bf16 = 8KB per split per buf; B: 128 rows = 8KB
    __shared__ unsigned sA[2 * NS * 2048];
    __shared__ unsigned sB[2 * NS * 2048];

    const int tid = threadIdx.x;
    const int m0 = blockIdx.y * 128;
    const int n0 = blockIdx.x * 128;

    const bf16* Bh = Bhi + (long)n0 * Kdim;
    const bf16* Bl = (NS == 2) ? (Blo + (long)n0 * Kdim) : nullptr;

    float* Cf; int ncol, epi;
    if (FUSED) {
        if (n0 < DD)          { Cf = CK; ncol = n0;      epi = 0; }
        else if (n0 < 2 * DD) { Cf = CQ; ncol = n0 - DD; epi = 0; }
        else                  { Cf = nullptr; ncol = n0; epi = epiH; }
    } else {
        Cf = CK; ncol = n0; epi = 0;
    }
    Ahi += (long)blockIdx.z * strideAz;
    if (NS == 2) Alo += (long)blockIdx.z * strideAz;
    if (Cf != nullptr) Cf += (long)blockIdx.z * strideCz;

    const int wid = tid >> 5, lane = tid & 31;
    const int wm = (wid >> 1) * 64, wn = (wid & 1) * 64;
    const int gr = lane >> 2, tg = lane & 3;

    unsigned sAb = (unsigned)__cvta_generic_to_shared(sA);
    unsigned sBb = (unsigned)__cvta_generic_to_shared(sB);

    // ldmatrix lane addresses: A frags (4 m16 per warp) x 2 k-halves, B (4 n16) x 2
    unsigned aAddr[2][4], bAddr[2][4];
    {
        const int t8 = lane & 7;
        const int q = lane >> 3;
#pragma unroll
        for (int h = 0; h < 2; h++) {
#pragma unroll
            for (int mi = 0; mi < 4; mi++) {
                int row = wm + mi * 16 + (q & 1) * 8 + t8;
                int ch = h * 2 + (q >> 1);
                int line = row >> 1;
                int slot = (row & 1) * 4 + (ch ^ (line & 3));
                aAddr[h][mi] = sAb + line * 128 + slot * 16;
            }
            int halfB = (lane >> 4) & 1, chB = (lane >> 3) & 1;
#pragma unroll
            for (int jp = 0; jp < 4; jp++) {
                int row = wn + jp * 16 + halfB * 8 + t8;
                int ch = h * 2 + chB;
                int line = row >> 1;
                int slot = (row & 1) * 4 + (ch ^ (line & 3));
                bAddr[h][jp] = sBb + line * 128 + slot * 16;
            }
        }
    }

    float acc[4][8][4];
#pragma unroll
    for (int i = 0; i < 4; i++)
#pragma unroll
        for (int j = 0; j < 8; j++)
#pragma unroll
            for (int t = 0; t < 4; t++) acc[i][j][t] = 0.f;

    auto loadG = [&](int k0, int buf) {
#pragma unroll
        for (int s = 0; s < NS; s++) {
            const bf16* src = (s == 0) ? Ahi : Alo;
#pragma unroll
            for (int i = 0; i < 4; i++) {       // A: 512 chunks / 128 thr
                int id = tid + i * 128;
                int row = id >> 2, ch = id & 3;
                int line = row >> 1;
                int slot = (row & 1) * 4 + (ch ^ (line & 3));
                unsigned sa = sAb + (buf * NS + s) * 8192 + line * 128 + slot * 16;
                int grow = m0 + row;
                bool ok = grow < Mrows;
                const bf16* gp = src + (long)(ok ? grow : 0) * Kdim + k0 + ch * 8;
                cpa16(sa, gp, ok ? 16 : 0);
            }
        }
#pragma unroll
        for (int s = 0; s < NS; s++) {
            const bf16* src = (s == 0) ? Bh : Bl;
#pragma unroll
            for (int i = 0; i < 4; i++) {       // B: 512 chunks / 128 thr
                int id = tid + i * 128;
                int row = id >> 2, ch = id & 3;
                int line = row >> 1;
                int slot = (row & 1) * 4 + (ch ^ (line & 3));
                unsigned sa = sBb + (buf * NS + s) * 8192 + line * 128 + slot * 16;
                cpa16(sa, src + (long)row * Kdim + k0 + ch * 8, 16);
            }
        }
        asm volatile("cp.async.commit_group;" ::: "memory");
    };

    auto compute = [&](int buf) {
#pragma unroll
        for (int h = 0; h < 2; h++) {
            unsigned a[NS][4][4], b[NS][8][2];
#pragma unroll
            for (int s = 0; s < NS; s++) {
                unsigned off = (unsigned)((buf * NS + s) * 8192);
#pragma unroll
                for (int mi = 0; mi < 4; mi++)
                    ldsm4(a[s][mi][0], a[s][mi][1], a[s][mi][2], a[s][mi][3],
                          aAddr[h][mi] + off);
#pragma unroll
                for (int jp = 0; jp < 4; jp++) {
                    unsigned r0, r1, r2, r3;
                    ldsm4(r0, r1, r2, r3, bAddr[h][jp] + off);
                    b[s][jp * 2][0] = r0; b[s][jp * 2][1] = r1;
                    b[s][jp * 2 + 1][0] = r2; b[s][jp * 2 + 1][1] = r3;
                }
            }
#pragma unroll
            for (int mi = 0; mi < 4; mi++)
#pragma unroll
                for (int j = 0; j < 8; j++) {
                    mma16(acc[mi][j], a[0][mi], b[0][j]);          // Ah*Bh
                    if (NS == 2) {
                        mma16(acc[mi][j], a[0][mi], b[NS - 1][j]); // Ah*Bl
                        mma16(acc[mi][j], a[NS - 1][mi], b[0][j]); // Al*Bh
                    }
                }
        }
    };

    const int nK = Kdim / 32;
    loadG(0, 0);
    for (int kt = 0; kt < nK; kt++) {
        int buf = kt & 1;
        asm volatile("cp.async.wait_group 0;" ::: "memory");
        __syncthreads();
        if (kt + 1 < nK) loadG((kt + 1) * 32, buf ^ 1);
        compute(buf);
    }

    if (epi == 0) {
#pragma unroll
        for (int mi = 0; mi < 4; mi++)
#pragma unroll
            for (int half = 0; half < 2; half++) {
                int row = m0 + wm + mi * 16 + half * 8 + gr;
                if (row >= Mrows) continue;
                float* Cr = Cf + (long)row * DD + ncol + wn;
#pragma unroll
                for (int j = 0; j < 8; j++) {
                    int col = j * 8 + tg * 2;
                    Cr[col]     = acc[mi][j][half * 2 + 0];
                    Cr[col + 1] = acc[mi][j][half * 2 + 1];
                }
            }
    } else {
        double le = 0.0;
#pragma unroll
        for (int mi = 0; mi < 4; mi++)
#pragma unroll
            for (int half = 0; half < 2; half++) {
                int row = m0 + wm + mi * 16 + half * 8 + gr;
                if (row >= Mrows) continue;
                long ob = (long)row * KCAT + ncol + wn;
#pragma unroll
                for (int j = 0; j < 8; j++) {
                    int col = j * 8 + tg * 2;
                    float c0 = acc[mi][j][half * 2 + 0];
                    float c1 = acc[mi][j][half * 2 + 1];
                    float r0 = c0 > 0.f ? c0 : 0.f;
                    float r1 = c1 > 0.f ? c1 : 0.f;
                    le += (double)r0 * (double)r0 + (double)r1 * (double)r1;
                    if (epi == 1) {
                        bf16 h, l;
                        hsplit(r0, h, l); CHhi[ob + col] = h;     CHlo[ob + col] = l;
                        hsplit(r1, h, l); CHhi[ob + col + 1] = h; CHlo[ob + col + 1] = l;
                    }
                }
            }
        __shared__ double ered[128];
        ered[tid] = le; __syncthreads();
        for (int o = 64; o; o >>= 1) {
            if (tid < o) ered[tid] += ered[tid + o];
            __syncthreads();
        }
        if (tid == 0)
            atomicAdd(e_base + (e_per_z ? blockIdx.z : 0), -0.5 * ered[0]);
    }
}

// ---------------- attention ----------------
#define ATT_LD 68
#define ATT_SMEM ((196*ATT_LD*2 + 196 + 8*200) * 4)

template <bool GRAD>
__global__ void __launch_bounds__(256)
att_kernel(const float* __restrict__ Kall, const float* __restrict__ Qall,
           bf16* __restrict__ dHi, bf16* __restrict__ dLo,
           double* e_base, int e_per_z) {
    extern __shared__ float sm[];
    const int LD = ATT_LD;
    float* Ksh = sm;
    float* Qsh = Ksh + 196 * LD;
    float* lse = Qsh + 196 * LD;
    float* rowbuf = lse + 196;
    __shared__ double wsum[8];

    int bh = blockIdx.x; int b = bh / NH; int h = bh % NH;
    long base = (long)blockIdx.z * NELEM + (long)b * NTOK * DD + h * HD;
    const float* Kg = Kall + base;
    const float* Qg = Qall + base;
    int tid = threadIdx.x, w = tid >> 5, lane = tid & 31;

    for (int i = tid; i < 196 * 16; i += 256) {
        int r = i >> 4, c4 = (i & 15) << 2;
        *(float4*)(Ksh + r * LD + c4) = *(const float4*)(Kg + (long)r * DD + c4);
        *(float4*)(Qsh + r * LD + c4) = *(const float4*)(Qg + (long)r * DD + c4);
    }
    __syncthreads();

    double lsesum = 0.0;
    float* rb = rowbuf + w * 200;

    for (int q = w; q < 196; q += 8) {
        const float4* Qr4 = (const float4*)(Qsh + q * LD);
        float mx = -1e30f;
        for (int k = lane; k < 196; k += 32) {
            const float4* Kr4 = (const float4*)(Ksh + k * LD);
            float s = 0.f;
#pragma unroll
            for (int y = 0; y < 16; y++) {
                float4 a = Kr4[y], b4 = Qr4[y];
                s = fmaf(a.x, b4.x, s); s = fmaf(a.y, b4.y, s);
                s = fmaf(a.z, b4.z, s); s = fmaf(a.w, b4.w, s);
            }
            s *= BETA;
            rb[k] = s;
            mx = fmaxf(mx, s);
        }
#pragma unroll
        for (int o = 16; o; o >>= 1) mx = fmaxf(mx, __shfl_xor_sync(0xffffffffu, mx, o));
        float se = 0.f;
        for (int k = lane; k < 196; k += 32) {
            float e = expf(rb[k] - mx);
            se += e;
            if (GRAD) rb[k] = e;
        }
#pragma unroll
        for (int o = 16; o; o >>= 1) se += __shfl_xor_sync(0xffffffffu, se, o);
        float l = mx + logf(se);
        if (lane == 0) lsesum += (double)l;
        if (GRAD) {
            if (lane == 0) lse[q] = l;
            float inv = 1.f / se;
            for (int k = lane; k < 196; k += 32) rb[k] *= inv;
            __syncwarp();
            int y0 = lane, y1 = lane + 32;
            float a0 = 0.f, a1 = 0.f;
            for (int k = 0; k < 196; k++) {
                float p = rb[k];
                a0 = fmaf(p, Ksh[k * LD + y0], a0);
                a1 = fmaf(p, Ksh[k * LD + y1], a1);
            }
            long o = (long)(b * NTOK + q) * KCAT + DD + h * HD;
            bf16 hh, ll;
            hsplit(-a0, hh, ll); dHi[o + y0] = hh; dLo[o + y0] = ll;
            hsplit(-a1, hh, ll); dHi[o + y1] = hh; dLo[o + y1] = ll;
            __syncwarp();
        }
    }

    if (lane == 0) wsum[w] = lsesum;
    __syncthreads();
    if (tid == 0) {
        double t = 0.0;
        for (int i = 0; i < 8; i++) t += wsum[i];
        atomicAdd(e_base + (e_per_z ? blockIdx.z : 0), -(double)INVB * t);
    }

    if (GRAD) {
        __syncthreads();   // lse[] complete
        for (int k = w; k < 196; k += 8) {
            const float4* Kr4 = (const float4*)(Ksh + k * LD);
            for (int q = lane; q < 196; q += 32) {
                const float4* Qr4 = (const float4*)(Qsh + q * LD);
                float s = 0.f;
#pragma unroll
                for (int y = 0; y < 16; y++) {
                    float4 a = Kr4[y], b4 = Qr4[y];
                    s = fmaf(a.x, b4.x, s); s = fmaf(a.y, b4.y, s);
                    s = fmaf(a.z, b4.z, s); s = fmaf(a.w, b4.w, s);
                }
                rb[q] = expf(BETA * s - lse[q]);
            }
            __syncwarp();
            int y0 = lane, y1 = lane + 32;
            float a0 = 0.f, a1 = 0.f;
            for (int q = 0; q < 196; q++) {
                float p = rb[q];
                a0 = fmaf(p, Qsh[q * LD + y0], a0);
                a1 = fmaf(p, Qsh[q * LD + y1], a1);
            }
            long o = (long)(b * NTOK + k) * KCAT + h * HD;
            bf16 hh, ll;
            hsplit(-a0, hh, ll); dHi[o + y0] = hh; dLo[o + y0] = ll;
            hsplit(-a1, hh, ll); dHi[o + y1] = hh; dLo[o + y1] = ll;
            __syncwarp();
        }
    }
}

// ---------------- host driver ----------------
extern "C" void kernel_launch(void* const* d_in, const int* in_sizes, int n_in,
                              void* d_out, int out_size) {
    const float* x     = (const float*)d_in[0];
    const float* gamma = (const float*)d_in[1];
    const float* delta = (const float*)d_in[2];
    const float* wk    = (const float*)d_in[3];
    const float* wq    = (const float*)d_in[4];
    const float* xi    = (const float*)d_in[5];
    float* out = (float*)d_out;

    bf16 *ghi, *glo, *Ahi, *Alo, *whi, *wlo, *BThi, *BTlo;
    float *K, *Q, *dg, *gr, *mean, *rstd;
    double *eref, *ecand;
    cudaGetSymbolAddress((void**)&ghi,  d_ghi);
    cudaGetSymbolAddress((void**)&glo,  d_glo);
    cudaGetSymbolAddress((void**)&K,    d_K);
    cudaGetSymbolAddress((void**)&Q,    d_Q);
    cudaGetSymbolAddress((void**)&Ahi,  d_Ahi);
    cudaGetSymbolAddress((void**)&Alo,  d_Alo);
    cudaGetSymbolAddress((void**)&whi,  d_whi);
    cudaGetSymbolAddress((void**)&wlo,  d_wlo);
    cudaGetSymbolAddress((void**)&BThi, d_BThi);
    cudaGetSymbolAddress((void**)&BTlo, d_BTlo);
    cudaGetSymbolAddress((void**)&dg,   d_dg);
    cudaGetSymbolAddress((void**)&gr,   d_gr);
    cudaGetSymbolAddress((void**)&mean, d_mean);
    cudaGetSymbolAddress((void**)&rstd, d_rstd);
    cudaGetSymbolAddress((void**)&eref,  d_eref);
    cudaGetSymbolAddress((void**)&ecand, d_ecand);

    cudaFuncSetAttribute(att_kernel<true>,  cudaFuncAttributeMaxDynamicSharedMemorySize, ATT_SMEM);
    cudaFuncSetAttribute(att_kernel<false>, cudaFuncAttributeMaxDynamicSharedMemorySize, ATT_SMEM);

    const long sZ = (long)NELEM;
    const int MB = (BN + 127) / 128;     // 13

    zero_kernel<<<1, 32>>>();

    // operand prep (bf16 hi/lo, once)
    w2bf_kernel<<<(int)(((long)KCAT * DD + 255) / 256), 256>>>(wk, wq, xi, whi, wlo);
    btprep_kernel<<<dim3(DD / 32, DD / 32), dim3(32, 8)>>>(wk, BThi, BTlo, 0, 1.f);
    btprep_kernel<<<dim3(DD / 32, DD / 32), dim3(32, 8)>>>(wq, BThi, BTlo, DD, 1.f);
    btprep_kernel<<<dim3(DD / 32, MHOP / 32), dim3(32, 8)>>>(xi, BThi, BTlo, 2 * DD, -1.f);

    // ---- main pass (split-3 bf16, near-fp32) ----
    ln_fwd_kernel<<<dim3(BN, 1, 1), 256>>>(x, nullptr, ghi, glo, gamma, delta, mean, rstd, 0);

    // fused K/Q/h: one N=4608 launch; h -> relu (bf16 hi/lo into Acat) + eref
    gemm_k<3, 1><<<dim3(KCAT / 128, MB), 128>>>(
        ghi, glo, whi, wlo, K, Q, Ahi, Alo,
        BN, DD, /*epiH=*/1, eref, 0, 0, 0);

    att_kernel<true><<<dim3(BB_ * NH, 1, 1), 256, ATT_SMEM>>>(K, Q, Ahi, Alo, eref, 0);

    // fused dgrad: dg = Acat @ BT^T   (K = 4608)
    gemm_k<3, 0><<<dim3(DD / 128, MB), 128>>>(
        Ahi, Alo, BThi, BTlo, dg, nullptr, nullptr, nullptr,
        BN, KCAT, /*epiH=*/0, nullptr, 0, 0, 0);

    ln_bwd_kernel<<<BN, 256>>>(x, mean, rstd, gamma, dg, gr);

    // ---- Armijo candidates (z = 4): single-term bf16, energies only ----
    ln_fwd_kernel<<<dim3(BN, 1, 4), 256>>>(x, gr, ghi, nullptr, gamma, delta, nullptr, nullptr, 1);

    gemm_k<1, 1><<<dim3(KCAT / 128, MB, 4), 128>>>(
        ghi, nullptr, whi, nullptr, K, Q, nullptr, nullptr,
        BN, DD, /*epiH=*/2, ecand, 1, sZ, sZ);

    att_kernel<false><<<dim3(BB_ * NH, 1, 4), 256, ATT_SMEM>>>(K, Q, nullptr, nullptr, ecand, 1);

    update_kernel<<<(NELEM + 255) / 256, 256>>>(x, gr, out);
}